// round 4
// baseline (speedup 1.0000x reference)
#include <cuda_runtime.h>
#include <cuda_fp16.h>

#define EMB   2048
#define NSTEP 2048
#define NB    2
#define G4    (4*EMB)

#define CTAS  128
#define EPC   16
#define NROWS 64
#define NTHR  512         // 16 warps: 8 row-groups x 2 K-halves
#define RPW   8           // rows per warp

// Per K-half (1024 cols = 512 f32-pairs), per row:
//   pairs [0,96)    cols [0,192)     registers (f32)     j  in [0,3)
//   pairs [96,288)  cols [192,576)   smem (f32)          jj in [0,3)  (2 pairs/thread/iter)
//   pairs [288,480) cols [576,960)   L2 stream (fp16)    jj in [0,3)  (2 pairs/thread/iter)
//   pairs [480,512) cols [960,1024)  L2 stream (fp16)    tail (1 pair/thread)

#define SH_W_F (NROWS*768)           // 64 rows x (384+384) cols  = 192KB
#define SH_H_F (NB*EMB)              // 16KB
#define SH_G_F (NROWS*2*2)           // [row][b][half]
#define SMEM_FLOATS (SH_W_F + SH_H_F + SH_G_F)
#define SMEM_BYTES  (SMEM_FLOATS*4)

__device__ float  g_Wcomb[(size_t)G4*EMB];      // f32 Wih+Whh
__device__ __half g_Whalf[(size_t)G4*EMB];      // fp16 copy
__device__ float  g_bcomb[G4];
__device__ float  g_hseq[(size_t)NSTEP*NB*EMB]; // [t][b][e]
__device__ int    g_flag[CTAS];

typedef unsigned long long ull;

__device__ __forceinline__ void ffma2(ull &d, ull a, ull b) {
    asm("fma.rn.f32x2 %0, %1, %2, %0;" : "+l"(d) : "l"(a), "l"(b));
}
__device__ __forceinline__ ull pack2(float lo, float hi) {
    ull r; asm("mov.b64 %0, {%1, %2};" : "=l"(r) : "f"(lo), "f"(hi)); return r;
}
__device__ __forceinline__ ull dup2(float a) {
    ull r; asm("mov.b64 %0, {%1, %1};" : "=l"(r) : "f"(a)); return r;
}
__device__ __forceinline__ float2 unpack2(ull v) {
    float2 f; asm("mov.b64 {%0, %1}, %2;" : "=f"(f.x), "=f"(f.y) : "l"(v)); return f;
}
__device__ __forceinline__ ull h2f2(unsigned u) {
    __half2 h = *reinterpret_cast<__half2*>(&u);
    float2 f = __half22float2(h);
    return pack2(f.x, f.y);
}
__device__ __forceinline__ float sigmoidf_(float v) {
    return 1.0f / (1.0f + expf(-v));
}

// ---------------------------------------------------------------------------
__global__ void prep_kernel(const float* __restrict__ Wih, const float* __restrict__ Whh,
                            const float* __restrict__ bih, const float* __restrict__ bhh) {
    size_t n = (size_t)G4 * EMB;
    size_t stride = (size_t)gridDim.x * blockDim.x;
    for (size_t i = (size_t)blockIdx.x * blockDim.x + threadIdx.x; i < n; i += stride) {
        float v = Wih[i] + Whh[i];
        g_Wcomb[i] = v;
        g_Whalf[i] = __float2half(v);
    }
    int i = blockIdx.x * blockDim.x + threadIdx.x;
    if (i < G4) g_bcomb[i] = bih[i] + bhh[i];
    if (i < CTAS) g_flag[i] = 0;
}

// ---------------------------------------------------------------------------
__global__ void __launch_bounds__(NTHR, 1)
lstm_kernel(const float* __restrict__ x, const float* __restrict__ Wih) {
    extern __shared__ float sh[];
    float* sh_w = sh;                    // [64][768]: [row][half*384 + lc]
    float* sh_h = sh + SH_W_F;           // [2][2048]
    float* sh_g = sh_h + SH_H_F;         // [row*2+b]*2 + half

    const int tid  = threadIdx.x;
    const int lane = tid & 31;
    const int w    = tid >> 5;
    const int half = w >> 3;             // K half
    const int rg   = w & 7;              // row group
    const int kb   = half * 1024;        // column base of this warp's half
    const int e0   = blockIdx.x * EPC;

    int Rg[RPW];
#pragma unroll
    for (int r = 0; r < RPW; r++) {
        int rl = rg * RPW + r;
        Rg[r] = (rl >> 4) * EMB + e0 + (rl & 15);
    }

    // fill smem weights: row rl, floats [0,768) = [half0 cols 192..575][half1 cols 1216..1599]
    for (int i = tid; i < NROWS * 192; i += NTHR) {
        int rr = i / 192, c4 = i % 192;
        int grow = (rr >> 4) * EMB + e0 + (rr & 15);
        int gcol = (c4 < 96) ? (192 + 4 * c4) : (1024 + 192 + 4 * (c4 - 96));
        float4 v = *(const float4*)&g_Wcomb[(size_t)grow * EMB + gcol];
        *(float4*)&sh_w[rr * 768 + c4 * 4] = v;
    }

    // register weights: pairs q = lane + 32*j, j<3 -> cols kb + 2q..2q+1
    ull wreg[RPW][3];
#pragma unroll
    for (int r = 0; r < RPW; r++)
#pragma unroll
        for (int j = 0; j < 3; j++)
            wreg[r][j] = *(const ull*)&g_Wcomb[(size_t)Rg[r] * EMB + kb + 2 * (lane + 32 * j)];

    float bias[4];
    float c_reg = 0.0f;
    const int my_el = tid >> 1, my_b = tid & 1;
    if (tid < 32) {
#pragma unroll
        for (int g = 0; g < 4; g++) bias[g] = g_bcomb[g * EMB + e0 + my_el];
    }

    const int rbase = rg * RPW;          // first local row of this warp

    for (int t = 0; t < NSTEP; t++) {
        // distributed grid barrier (skip at t=0; prep zeroed flags)
        if (t > 0) {
            if (tid < CTAS) {
                while (((volatile int*)g_flag)[tid] < t) { }
            }
            __threadfence();
        }
        __syncthreads();

        // stage h_{t-1} (or x) into smem
        {
            const float* src = (t == 0) ? x : &g_hseq[(size_t)(t - 1) * NB * EMB];
            const float4* s4 = (const float4*)src;
            float4* d4 = (float4*)sh_h;
            d4[tid]        = __ldcg(s4 + tid);
            d4[tid + NTHR] = __ldcg(s4 + tid + NTHR);
        }
        __syncthreads();

        ull acc[RPW][2];
#pragma unroll
        for (int r = 0; r < RPW; r++) { acc[r][0] = 0ull; acc[r][1] = 0ull; }

        if (t == 0) {
            // gates0 = x @ W_ih^T over this warp's K half
            for (int j = 0; j < 16; j++) {
                int col = kb + 2 * (lane + 32 * j);
                ull ha = *(const ull*)&sh_h[col];
                ull hb = *(const ull*)&sh_h[EMB + col];
#pragma unroll
                for (int r = 0; r < RPW; r++) {
                    ull wv = __ldg((const ull*)&Wih[(size_t)Rg[r] * EMB + col]);
                    ffma2(acc[r][0], wv, ha);
                    ffma2(acc[r][1], wv, hb);
                }
            }
        } else {
            // ---- phase A: register weights ----
#pragma unroll
            for (int j = 0; j < 3; j++) {
                int col = kb + 2 * (lane + 32 * j);
                ull ha = *(const ull*)&sh_h[col];
                ull hb = *(const ull*)&sh_h[EMB + col];
#pragma unroll
                for (int r = 0; r < RPW; r++) {
                    ffma2(acc[r][0], wreg[r][j], ha);
                    ffma2(acc[r][1], wreg[r][j], hb);
                }
            }

            // ---- phases B (smem) + C (fp16 L2), interleaved, 1-deep prefetch ----
            uint2 cw[RPW];
#pragma unroll
            for (int r = 0; r < RPW; r++)
                cw[r] = __ldg((const uint2*)&g_Whalf[(size_t)Rg[r] * EMB + kb + 576 + 4 * lane]);

#pragma unroll
            for (int jj = 0; jj < 3; jj++) {
                // B jj: smem cols kb + 192 + 4*lane + 128*jj (2 pairs)
                {
                    int col = kb + 192 + 4 * lane + 128 * jj;
                    float4 hA4 = *(const float4*)&sh_h[col];
                    float4 hB4 = *(const float4*)&sh_h[EMB + col];
                    ull hA0 = pack2(hA4.x, hA4.y), hA1 = pack2(hA4.z, hA4.w);
                    ull hB0 = pack2(hB4.x, hB4.y), hB1 = pack2(hB4.z, hB4.w);
                    int sc = half * 384 + 4 * lane + 128 * jj;
#pragma unroll
                    for (int r = 0; r < RPW; r++) {
                        float4 wv = *(const float4*)&sh_w[(rbase + r) * 768 + sc];
                        ull w0 = pack2(wv.x, wv.y), w1 = pack2(wv.z, wv.w);
                        ffma2(acc[r][0], w0, hA0); ffma2(acc[r][0], w1, hA1);
                        ffma2(acc[r][1], w0, hB0); ffma2(acc[r][1], w1, hB1);
                    }
                }
                // C jj: consume prefetched fp16, prefetch next
                {
                    uint2 cur[RPW];
#pragma unroll
                    for (int r = 0; r < RPW; r++) cur[r] = cw[r];
                    if (jj < 2) {
#pragma unroll
                        for (int r = 0; r < RPW; r++)
                            cw[r] = __ldg((const uint2*)&g_Whalf[(size_t)Rg[r] * EMB + kb + 576 + 4 * lane + 128 * (jj + 1)]);
                    }
                    int col = kb + 576 + 4 * lane + 128 * jj;
                    float4 hA4 = *(const float4*)&sh_h[col];
                    float4 hB4 = *(const float4*)&sh_h[EMB + col];
                    ull hA0 = pack2(hA4.x, hA4.y), hA1 = pack2(hA4.z, hA4.w);
                    ull hB0 = pack2(hB4.x, hB4.y), hB1 = pack2(hB4.z, hB4.w);
#pragma unroll
                    for (int r = 0; r < RPW; r++) {
                        ull w0 = h2f2(cur[r].x), w1 = h2f2(cur[r].y);
                        ffma2(acc[r][0], w0, hA0); ffma2(acc[r][0], w1, hA1);
                        ffma2(acc[r][1], w0, hB0); ffma2(acc[r][1], w1, hB1);
                    }
                }
            }

            // ---- C tail: pairs [480,512): col = kb + 960 + 2*lane (1 pair) ----
            {
                int col = kb + 960 + 2 * lane;
                ull ha = *(const ull*)&sh_h[col];
                ull hb = *(const ull*)&sh_h[EMB + col];
#pragma unroll
                for (int r = 0; r < RPW; r++) {
                    unsigned cv = __ldg((const unsigned*)&g_Whalf[(size_t)Rg[r] * EMB + col]);
                    ull w0 = h2f2(cv);
                    ffma2(acc[r][0], w0, ha);
                    ffma2(acc[r][1], w0, hb);
                }
            }
        }

        // warp reduce -> sh_g[(rl*2+b)*2 + half]
#pragma unroll
        for (int r = 0; r < RPW; r++) {
#pragma unroll
            for (int b = 0; b < 2; b++) {
                float2 f = unpack2(acc[r][b]);
                float v = f.x + f.y;
                v += __shfl_xor_sync(0xffffffffu, v, 16);
                v += __shfl_xor_sync(0xffffffffu, v, 8);
                v += __shfl_xor_sync(0xffffffffu, v, 4);
                v += __shfl_xor_sync(0xffffffffu, v, 2);
                v += __shfl_xor_sync(0xffffffffu, v, 1);
                if (lane == 0) sh_g[((rbase + r) * 2 + b) * 2 + half] = v;
            }
        }
        __syncthreads();

        // owners: combine halves, activation, state update, publish h
        if (tid < 32) {
            float gi = sh_g[((0 * 16 + my_el) * 2 + my_b) * 2] + sh_g[((0 * 16 + my_el) * 2 + my_b) * 2 + 1] + bias[0];
            float gf = sh_g[((1 * 16 + my_el) * 2 + my_b) * 2] + sh_g[((1 * 16 + my_el) * 2 + my_b) * 2 + 1] + bias[1];
            float gg = sh_g[((2 * 16 + my_el) * 2 + my_b) * 2] + sh_g[((2 * 16 + my_el) * 2 + my_b) * 2 + 1] + bias[2];
            float go = sh_g[((3 * 16 + my_el) * 2 + my_b) * 2] + sh_g[((3 * 16 + my_el) * 2 + my_b) * 2 + 1] + bias[3];
            float cn = sigmoidf_(gf) * c_reg + sigmoidf_(gi) * tanhf(gg);
            c_reg = cn;
            float h = sigmoidf_(go) * tanhf(cn);
            g_hseq[((size_t)t * NB + my_b) * EMB + e0 + my_el] = h;
        }
        __threadfence();
        __syncthreads();
        if (tid == 0) ((volatile int*)g_flag)[blockIdx.x] = t + 1;
    }
}

// ---------------------------------------------------------------------------
// output projection: out[b][t][n] = hseq[t][b][:] . W_out[n][:] + b_out[n]
// M = 4096 (m = t*2+b), N = 2048, K = 2048, FFMA2 micro-kernel
// ---------------------------------------------------------------------------
#define GBM 64
#define GBN 64
#define GBK 16
#define GPAD 4

__global__ void __launch_bounds__(256)
out_gemm_kernel(const float* __restrict__ Wout, const float* __restrict__ bout,
                float* __restrict__ out) {
    __shared__ float As[GBK][GBM + GPAD];
    __shared__ float Bs[GBK][GBN + GPAD];

    const int tid = threadIdx.x;
    const int tx = tid & 15;
    const int ty = tid >> 4;
    const int m0 = blockIdx.y * GBM;
    const int n0 = blockIdx.x * GBN;

    ull accL[4], accH[4];
#pragma unroll
    for (int i = 0; i < 4; i++) { accL[i] = 0ull; accH[i] = 0ull; }

    const int lm = tid >> 2;
    const int lk = (tid & 3) * 4;

    for (int k0 = 0; k0 < EMB; k0 += GBK) {
        float4 va = *(const float4*)&g_hseq[(size_t)(m0 + lm) * EMB + k0 + lk];
        float4 vb = *(const float4*)&Wout[(size_t)(n0 + lm) * EMB + k0 + lk];
        As[lk + 0][lm] = va.x; As[lk + 1][lm] = va.y;
        As[lk + 2][lm] = va.z; As[lk + 3][lm] = va.w;
        Bs[lk + 0][lm] = vb.x; Bs[lk + 1][lm] = vb.y;
        Bs[lk + 2][lm] = vb.z; Bs[lk + 3][lm] = vb.w;
        __syncthreads();

#pragma unroll
        for (int k = 0; k < GBK; k++) {
            float4 b4 = *(const float4*)&Bs[k][tx * 4];
            ull bL = pack2(b4.x, b4.y);
            ull bH = pack2(b4.z, b4.w);
#pragma unroll
            for (int i = 0; i < 4; i++) {
                ull ai = dup2(As[k][ty * 4 + i]);
                ffma2(accL[i], ai, bL);
                ffma2(accH[i], ai, bH);
            }
        }
        __syncthreads();
    }

#pragma unroll
    for (int i = 0; i < 4; i++) {
        int m = m0 + ty * 4 + i;
        int tt = m >> 1, bb = m & 1;
        float2 l = unpack2(accL[i]);
        float2 h = unpack2(accH[i]);
        float* o = &out[((size_t)bb * NSTEP + tt) * EMB + n0 + tx * 4];
        o[0] = l.x + bout[n0 + tx * 4 + 0];
        o[1] = l.y + bout[n0 + tx * 4 + 1];
        o[2] = h.x + bout[n0 + tx * 4 + 2];
        o[3] = h.y + bout[n0 + tx * 4 + 3];
    }
}

// ---------------------------------------------------------------------------
extern "C" void kernel_launch(void* const* d_in, const int* in_sizes, int n_in,
                              void* d_out, int out_size) {
    const float* x    = (const float*)d_in[0];
    const float* Wih  = (const float*)d_in[1];
    const float* Whh  = (const float*)d_in[2];
    const float* bih  = (const float*)d_in[3];
    const float* bhh  = (const float*)d_in[4];
    const float* Wout = (const float*)d_in[5];
    const float* bout = (const float*)d_in[6];
    float* out = (float*)d_out;

    cudaFuncSetAttribute(lstm_kernel, cudaFuncAttributeMaxDynamicSharedMemorySize, SMEM_BYTES);

    prep_kernel<<<4096, 256>>>(Wih, Whh, bih, bhh);
    lstm_kernel<<<CTAS, NTHR, SMEM_BYTES>>>(x, Wih);
    dim3 ggrid(EMB / GBN, (NSTEP * NB) / GBM);
    out_gemm_kernel<<<ggrid, 256>>>(Wout, bout, out);
}

// round 5
// speedup vs baseline: 1.0748x; 1.0748x over previous
#include <cuda_runtime.h>
#include <cuda_fp16.h>

#define EMB   2048
#define NSTEP 2048
#define NB    2
#define G4    (4*EMB)

#define CTAS  128
#define EPC   16
#define NROWS 64
#define NTHR  512         // 16 warps: 8 row-groups x 2 K-halves
#define RPW   8           // rows per warp

// Per K-half (1024 cols = 512 f32-pairs), per row:
//   pairs [0,96)    cols [0,192)     registers (f32)     j  in [0,3)
//   pairs [96,288)  cols [192,576)   smem (f32)          jj in [0,3)  (2 pairs/thread/iter)
//   pairs [288,480) cols [576,960)   L2 stream (fp16)    jj in [0,3)  (2 pairs/thread/iter)
//   pairs [480,512) cols [960,1024)  L2 stream (fp16)    tail (1 pair/thread)

#define SH_W_F (NROWS*768)           // 64 rows x (384+384) cols  = 192KB
#define SH_H_F (NB*EMB)              // 16KB
#define SH_G_F (NROWS*2*2)           // [row][b][half]
#define SMEM_FLOATS (SH_W_F + SH_H_F + SH_G_F)
#define SMEM_BYTES  (SMEM_FLOATS*4)

__device__ float  g_Wcomb[(size_t)G4*EMB];      // f32 Wih+Whh
__device__ __half g_Whalf[(size_t)G4*EMB];      // fp16 copy
__device__ float  g_bcomb[G4];
__device__ float  g_hseq[(size_t)NSTEP*NB*EMB]; // [t][b][e]
__device__ int    g_flag[CTAS];

typedef unsigned long long ull;

__device__ __forceinline__ void ffma2(ull &d, ull a, ull b) {
    asm("fma.rn.f32x2 %0, %1, %2, %0;" : "+l"(d) : "l"(a), "l"(b));
}
__device__ __forceinline__ ull pack2(float lo, float hi) {
    ull r; asm("mov.b64 %0, {%1, %2};" : "=l"(r) : "f"(lo), "f"(hi)); return r;
}
__device__ __forceinline__ ull dup2(float a) {
    ull r; asm("mov.b64 %0, {%1, %1};" : "=l"(r) : "f"(a)); return r;
}
__device__ __forceinline__ float2 unpack2(ull v) {
    float2 f; asm("mov.b64 {%0, %1}, %2;" : "=f"(f.x), "=f"(f.y) : "l"(v)); return f;
}
__device__ __forceinline__ ull h2f2(unsigned u) {
    __half2 h = *reinterpret_cast<__half2*>(&u);
    float2 f = __half22float2(h);
    return pack2(f.x, f.y);
}
__device__ __forceinline__ float sigmoidf_(float v) {
    return 1.0f / (1.0f + expf(-v));
}

// ---------------------------------------------------------------------------
__global__ void prep_kernel(const float* __restrict__ Wih, const float* __restrict__ Whh,
                            const float* __restrict__ bih, const float* __restrict__ bhh) {
    size_t n = (size_t)G4 * EMB;
    size_t stride = (size_t)gridDim.x * blockDim.x;
    for (size_t i = (size_t)blockIdx.x * blockDim.x + threadIdx.x; i < n; i += stride) {
        float v = Wih[i] + Whh[i];
        g_Wcomb[i] = v;
        g_Whalf[i] = __float2half(v);
    }
    int i = blockIdx.x * blockDim.x + threadIdx.x;
    if (i < G4) g_bcomb[i] = bih[i] + bhh[i];
    if (i < CTAS) g_flag[i] = 0;
}

// ---------------------------------------------------------------------------
__global__ void __launch_bounds__(NTHR, 1)
lstm_kernel(const float* __restrict__ x, const float* __restrict__ Wih) {
    extern __shared__ float sh[];
    float* sh_w = sh;                    // [64][768]: [row][half*384 + lc]
    float* sh_h = sh + SH_W_F;           // [2][2048]
    float* sh_g = sh_h + SH_H_F;         // [row*2+b]*2 + half

    const int tid  = threadIdx.x;
    const int lane = tid & 31;
    const int w    = tid >> 5;
    const int half = w >> 3;             // K half
    const int rg   = w & 7;              // row group
    const int kb   = half * 1024;        // column base of this warp's half
    const int e0   = blockIdx.x * EPC;

    int Rg[RPW];
#pragma unroll
    for (int r = 0; r < RPW; r++) {
        int rl = rg * RPW + r;
        Rg[r] = (rl >> 4) * EMB + e0 + (rl & 15);
    }

    // fill smem weights: row rl, floats [0,768) = [half0 cols 192..575][half1 cols 1216..1599]
    for (int i = tid; i < NROWS * 192; i += NTHR) {
        int rr = i / 192, c4 = i % 192;
        int grow = (rr >> 4) * EMB + e0 + (rr & 15);
        int gcol = (c4 < 96) ? (192 + 4 * c4) : (1024 + 192 + 4 * (c4 - 96));
        float4 v = *(const float4*)&g_Wcomb[(size_t)grow * EMB + gcol];
        *(float4*)&sh_w[rr * 768 + c4 * 4] = v;
    }

    // register weights: pairs q = lane + 32*j, j<3 -> cols kb + 2q..2q+1
    ull wreg[RPW][3];
#pragma unroll
    for (int r = 0; r < RPW; r++)
#pragma unroll
        for (int j = 0; j < 3; j++)
            wreg[r][j] = *(const ull*)&g_Wcomb[(size_t)Rg[r] * EMB + kb + 2 * (lane + 32 * j)];

    float bias[4];
    float c_reg = 0.0f;
    const int my_el = tid >> 1, my_b = tid & 1;
    if (tid < 32) {
#pragma unroll
        for (int g = 0; g < 4; g++) bias[g] = g_bcomb[g * EMB + e0 + my_el];
    }

    const int rbase = rg * RPW;          // first local row of this warp

    for (int t = 0; t < NSTEP; t++) {
        // distributed grid barrier (skip at t=0; prep zeroed flags)
        if (t > 0) {
            if (tid < CTAS) {
                while (((volatile int*)g_flag)[tid] < t) { }
            }
            __threadfence();
        }
        __syncthreads();

        // stage h_{t-1} (or x) into smem
        {
            const float* src = (t == 0) ? x : &g_hseq[(size_t)(t - 1) * NB * EMB];
            const float4* s4 = (const float4*)src;
            float4* d4 = (float4*)sh_h;
            d4[tid]        = __ldcg(s4 + tid);
            d4[tid + NTHR] = __ldcg(s4 + tid + NTHR);
        }
        __syncthreads();

        ull acc[RPW][2];
#pragma unroll
        for (int r = 0; r < RPW; r++) { acc[r][0] = 0ull; acc[r][1] = 0ull; }

        if (t == 0) {
            // gates0 = x @ W_ih^T over this warp's K half
            for (int j = 0; j < 16; j++) {
                int col = kb + 2 * (lane + 32 * j);
                ull ha = *(const ull*)&sh_h[col];
                ull hb = *(const ull*)&sh_h[EMB + col];
#pragma unroll
                for (int r = 0; r < RPW; r++) {
                    ull wv = __ldg((const ull*)&Wih[(size_t)Rg[r] * EMB + col]);
                    ffma2(acc[r][0], wv, ha);
                    ffma2(acc[r][1], wv, hb);
                }
            }
        } else {
            // ---- phase A: register weights ----
#pragma unroll
            for (int j = 0; j < 3; j++) {
                int col = kb + 2 * (lane + 32 * j);
                ull ha = *(const ull*)&sh_h[col];
                ull hb = *(const ull*)&sh_h[EMB + col];
#pragma unroll
                for (int r = 0; r < RPW; r++) {
                    ffma2(acc[r][0], wreg[r][j], ha);
                    ffma2(acc[r][1], wreg[r][j], hb);
                }
            }

            // ---- phases B (smem) + C (fp16 L2), interleaved, 1-deep prefetch ----
            uint2 cw[RPW];
#pragma unroll
            for (int r = 0; r < RPW; r++)
                cw[r] = __ldg((const uint2*)&g_Whalf[(size_t)Rg[r] * EMB + kb + 576 + 4 * lane]);

#pragma unroll
            for (int jj = 0; jj < 3; jj++) {
                // B jj: smem cols kb + 192 + 4*lane + 128*jj (2 pairs)
                {
                    int col = kb + 192 + 4 * lane + 128 * jj;
                    float4 hA4 = *(const float4*)&sh_h[col];
                    float4 hB4 = *(const float4*)&sh_h[EMB + col];
                    ull hA0 = pack2(hA4.x, hA4.y), hA1 = pack2(hA4.z, hA4.w);
                    ull hB0 = pack2(hB4.x, hB4.y), hB1 = pack2(hB4.z, hB4.w);
                    int sc = half * 384 + 4 * lane + 128 * jj;
#pragma unroll
                    for (int r = 0; r < RPW; r++) {
                        float4 wv = *(const float4*)&sh_w[(rbase + r) * 768 + sc];
                        ull w0 = pack2(wv.x, wv.y), w1 = pack2(wv.z, wv.w);
                        ffma2(acc[r][0], w0, hA0); ffma2(acc[r][0], w1, hA1);
                        ffma2(acc[r][1], w0, hB0); ffma2(acc[r][1], w1, hB1);
                    }
                }
                // C jj: consume prefetched fp16, prefetch next
                {
                    uint2 cur[RPW];
#pragma unroll
                    for (int r = 0; r < RPW; r++) cur[r] = cw[r];
                    if (jj < 2) {
#pragma unroll
                        for (int r = 0; r < RPW; r++)
                            cw[r] = __ldg((const uint2*)&g_Whalf[(size_t)Rg[r] * EMB + kb + 576 + 4 * lane + 128 * (jj + 1)]);
                    }
                    int col = kb + 576 + 4 * lane + 128 * jj;
                    float4 hA4 = *(const float4*)&sh_h[col];
                    float4 hB4 = *(const float4*)&sh_h[EMB + col];
                    ull hA0 = pack2(hA4.x, hA4.y), hA1 = pack2(hA4.z, hA4.w);
                    ull hB0 = pack2(hB4.x, hB4.y), hB1 = pack2(hB4.z, hB4.w);
#pragma unroll
                    for (int r = 0; r < RPW; r++) {
                        ull w0 = h2f2(cur[r].x), w1 = h2f2(cur[r].y);
                        ffma2(acc[r][0], w0, hA0); ffma2(acc[r][0], w1, hA1);
                        ffma2(acc[r][1], w0, hB0); ffma2(acc[r][1], w1, hB1);
                    }
                }
            }

            // ---- C tail: pairs [480,512): col = kb + 960 + 2*lane (1 pair) ----
            {
                int col = kb + 960 + 2 * lane;
                ull ha = *(const ull*)&sh_h[col];
                ull hb = *(const ull*)&sh_h[EMB + col];
#pragma unroll
                for (int r = 0; r < RPW; r++) {
                    unsigned cv = __ldg((const unsigned*)&g_Whalf[(size_t)Rg[r] * EMB + col]);
                    ull w0 = h2f2(cv);
                    ffma2(acc[r][0], w0, ha);
                    ffma2(acc[r][1], w0, hb);
                }
            }
        }

        // warp reduce -> sh_g[(rl*2+b)*2 + half]
#pragma unroll
        for (int r = 0; r < RPW; r++) {
#pragma unroll
            for (int b = 0; b < 2; b++) {
                float2 f = unpack2(acc[r][b]);
                float v = f.x + f.y;
                v += __shfl_xor_sync(0xffffffffu, v, 16);
                v += __shfl_xor_sync(0xffffffffu, v, 8);
                v += __shfl_xor_sync(0xffffffffu, v, 4);
                v += __shfl_xor_sync(0xffffffffu, v, 2);
                v += __shfl_xor_sync(0xffffffffu, v, 1);
                if (lane == 0) sh_g[((rbase + r) * 2 + b) * 2 + half] = v;
            }
        }
        __syncthreads();

        // owners: combine halves, activation, state update, publish h
        if (tid < 32) {
            float gi = sh_g[((0 * 16 + my_el) * 2 + my_b) * 2] + sh_g[((0 * 16 + my_el) * 2 + my_b) * 2 + 1] + bias[0];
            float gf = sh_g[((1 * 16 + my_el) * 2 + my_b) * 2] + sh_g[((1 * 16 + my_el) * 2 + my_b) * 2 + 1] + bias[1];
            float gg = sh_g[((2 * 16 + my_el) * 2 + my_b) * 2] + sh_g[((2 * 16 + my_el) * 2 + my_b) * 2 + 1] + bias[2];
            float go = sh_g[((3 * 16 + my_el) * 2 + my_b) * 2] + sh_g[((3 * 16 + my_el) * 2 + my_b) * 2 + 1] + bias[3];
            float cn = sigmoidf_(gf) * c_reg + sigmoidf_(gi) * tanhf(gg);
            c_reg = cn;
            float h = sigmoidf_(go) * tanhf(cn);
            g_hseq[((size_t)t * NB + my_b) * EMB + e0 + my_el] = h;
        }
        __threadfence();
        __syncthreads();
        if (tid == 0) ((volatile int*)g_flag)[blockIdx.x] = t + 1;
    }
}

// ---------------------------------------------------------------------------
// output projection: out[b][t][n] = hseq[t][b][:] . W_out[n][:] + b_out[n]
// M = 4096 (m = t*2+b), N = 2048, K = 2048, FFMA2 micro-kernel
// ---------------------------------------------------------------------------
#define GBM 64
#define GBN 64
#define GBK 16
#define GPAD 4

__global__ void __launch_bounds__(256)
out_gemm_kernel(const float* __restrict__ Wout, const float* __restrict__ bout,
                float* __restrict__ out) {
    __shared__ float As[GBK][GBM + GPAD];
    __shared__ float Bs[GBK][GBN + GPAD];

    const int tid = threadIdx.x;
    const int tx = tid & 15;
    const int ty = tid >> 4;
    const int m0 = blockIdx.y * GBM;
    const int n0 = blockIdx.x * GBN;

    ull accL[4], accH[4];
#pragma unroll
    for (int i = 0; i < 4; i++) { accL[i] = 0ull; accH[i] = 0ull; }

    const int lm = tid >> 2;
    const int lk = (tid & 3) * 4;

    for (int k0 = 0; k0 < EMB; k0 += GBK) {
        float4 va = *(const float4*)&g_hseq[(size_t)(m0 + lm) * EMB + k0 + lk];
        float4 vb = *(const float4*)&Wout[(size_t)(n0 + lm) * EMB + k0 + lk];
        As[lk + 0][lm] = va.x; As[lk + 1][lm] = va.y;
        As[lk + 2][lm] = va.z; As[lk + 3][lm] = va.w;
        Bs[lk + 0][lm] = vb.x; Bs[lk + 1][lm] = vb.y;
        Bs[lk + 2][lm] = vb.z; Bs[lk + 3][lm] = vb.w;
        __syncthreads();

#pragma unroll
        for (int k = 0; k < GBK; k++) {
            float4 b4 = *(const float4*)&Bs[k][tx * 4];
            ull bL = pack2(b4.x, b4.y);
            ull bH = pack2(b4.z, b4.w);
#pragma unroll
            for (int i = 0; i < 4; i++) {
                ull ai = dup2(As[k][ty * 4 + i]);
                ffma2(accL[i], ai, bL);
                ffma2(accH[i], ai, bH);
            }
        }
        __syncthreads();
    }

#pragma unroll
    for (int i = 0; i < 4; i++) {
        int m = m0 + ty * 4 + i;
        int tt = m >> 1, bb = m & 1;
        float2 l = unpack2(accL[i]);
        float2 h = unpack2(accH[i]);
        float* o = &out[((size_t)bb * NSTEP + tt) * EMB + n0 + tx * 4];
        o[0] = l.x + bout[n0 + tx * 4 + 0];
        o[1] = l.y + bout[n0 + tx * 4 + 1];
        o[2] = h.x + bout[n0 + tx * 4 + 2];
        o[3] = h.y + bout[n0 + tx * 4 + 3];
    }
}

// ---------------------------------------------------------------------------
extern "C" void kernel_launch(void* const* d_in, const int* in_sizes, int n_in,
                              void* d_out, int out_size) {
    const float* x    = (const float*)d_in[0];
    const float* Wih  = (const float*)d_in[1];
    const float* Whh  = (const float*)d_in[2];
    const float* bih  = (const float*)d_in[3];
    const float* bhh  = (const float*)d_in[4];
    const float* Wout = (const float*)d_in[5];
    const float* bout = (const float*)d_in[6];
    float* out = (float*)d_out;

    cudaFuncSetAttribute(lstm_kernel, cudaFuncAttributeMaxDynamicSharedMemorySize, SMEM_BYTES);

    prep_kernel<<<4096, 256>>>(Wih, Whh, bih, bhh);
    lstm_kernel<<<CTAS, NTHR, SMEM_BYTES>>>(x, Wih);
    dim3 ggrid(EMB / GBN, (NSTEP * NB) / GBM);
    out_gemm_kernel<<<ggrid, 256>>>(Wout, bout, out);
}

// round 6
// speedup vs baseline: 2.4124x; 2.2446x over previous
#include <cuda_runtime.h>
#include <cuda_fp16.h>

#define EMB   2048
#define NSTEP 2048
#define NB    2
#define G4    (4*EMB)

#define CTAS  128
#define EPC   16          // e-values per CTA
#define NROWS 64          // 4 gates * EPC
#define NTHR  512         // 16 warps
#define RPW   4           // rows per warp, each warp covers full K

// K partition per row (2048 cols):
//   cols [0,512)     f32 in registers  (k = lane + 32*j, j in [0,16))
//   cols [512,2048)  fp16 in smem      (pair p = lane + 32*jp, jp in [0,24))

#define SH_W_U (NROWS*768)          // 49152 uints (fp16x2) = 192KB
#define SH_H_F (NB*EMB)             // 4096 floats = 16KB
#define SH_G_F (NROWS*2)
#define SMEM_BYTES (SH_W_U*4 + SH_H_F*4 + SH_G_F*4)

__device__ float  g_Wcomb[(size_t)G4*EMB];      // f32 Wih+Whh
__device__ __half g_Whalf[(size_t)G4*EMB];      // fp16 copy
__device__ float  g_bcomb[G4];
__device__ float  g_hseq[(size_t)NSTEP*NB*EMB]; // [t][b][e]
__device__ unsigned g_bar;

__device__ __forceinline__ float sigmoidf_(float v) {
    return 1.0f / (1.0f + expf(-v));
}

// ---------------------------------------------------------------------------
__global__ void prep_kernel(const float* __restrict__ Wih, const float* __restrict__ Whh,
                            const float* __restrict__ bih, const float* __restrict__ bhh) {
    size_t n = (size_t)G4 * EMB;
    size_t stride = (size_t)gridDim.x * blockDim.x;
    for (size_t i = (size_t)blockIdx.x * blockDim.x + threadIdx.x; i < n; i += stride) {
        float v = Wih[i] + Whh[i];
        g_Wcomb[i] = v;
        g_Whalf[i] = __float2half(v);
    }
    int i = blockIdx.x * blockDim.x + threadIdx.x;
    if (i < G4) g_bcomb[i] = bih[i] + bhh[i];
    if (i == 0) g_bar = 0u;
}

// ---------------------------------------------------------------------------
// persistent LSTM: 128 CTAs x 512 threads (16 warps, 4/SMSP), occupancy 1.
// Warp w owns rows w*4..w*4+3 over the FULL K. No steady-state global weight
// reads: cols [0,512) live in registers (f32), cols [512,2048) in smem (fp16).
// ---------------------------------------------------------------------------
__global__ void __launch_bounds__(NTHR, 1)
lstm_kernel(const float* __restrict__ x, const float* __restrict__ Wih) {
    extern __shared__ float sh[];
    unsigned* sh_w = (unsigned*)sh;          // [64][768] fp16x2, cols [512,2048)
    float* sh_h = sh + SH_W_U;               // [2][2048]
    float* sh_g = sh_h + SH_H_F;             // [64][2]

    const int tid  = threadIdx.x;
    const int lane = tid & 31;
    const int wid  = tid >> 5;
    const int e0   = blockIdx.x * EPC;

    int rl[RPW], Rg[RPW];
    float bias[RPW];
#pragma unroll
    for (int r = 0; r < RPW; r++) {
        rl[r] = wid * RPW + r;
        int gate = rl[r] >> 4, e_l = rl[r] & 15;
        Rg[r] = gate * EMB + e0 + e_l;
        bias[r] = g_bcomb[Rg[r]];
    }

    // fill smem fp16 weights: cols [512,2048) for the CTA's 64 rows
    {
        const int n4 = NROWS * 192;          // uint4 count (8 halves each)
        for (int i = tid; i < n4; i += NTHR) {
            int rr = i / 192, q4 = i % 192;
            int grow = (rr >> 4) * EMB + e0 + (rr & 15);
            uint4 v = *(const uint4*)&g_Whalf[(size_t)grow * EMB + 512 + q4 * 8];
            ((uint4*)sh_w)[rr * 192 + q4] = v;
        }
    }

    // register-resident f32 weights: k = lane + 32*j, j in [0,16)
    float wreg[RPW][16];
#pragma unroll
    for (int r = 0; r < RPW; r++)
#pragma unroll
        for (int j = 0; j < 16; j++)
            wreg[r][j] = g_Wcomb[(size_t)Rg[r] * EMB + (lane + 32 * j)];

    float c_reg = 0.0f;
    const int my_el = tid >> 1, my_b = tid & 1;

    for (int t = 0; t < NSTEP; t++) {
        // stage h_{t-1} (or x) into smem
        const float* src = (t == 0) ? x : &g_hseq[(size_t)(t - 1) * NB * EMB];
        {
            const float4* s4 = (const float4*)src;
            float4* d4 = (float4*)sh_h;
            d4[tid]        = __ldcg(s4 + tid);
            d4[tid + NTHR] = __ldcg(s4 + tid + NTHR);
        }
        __syncthreads();

        float acc[RPW][2];
#pragma unroll
        for (int r = 0; r < RPW; r++) { acc[r][0] = 0.0f; acc[r][1] = 0.0f; }

        if (t == 0) {
            // gates0 = x @ W_ih^T (h0 = 0): stream W_ih f32 once
#pragma unroll 4
            for (int j = 0; j < 64; j++) {
                int k = lane + 32 * j;
                float h0 = sh_h[k], h1 = sh_h[EMB + k];
#pragma unroll
                for (int r = 0; r < RPW; r++) {
                    float w = __ldg(&Wih[(size_t)Rg[r] * EMB + k]);
                    acc[r][0] += w * h0; acc[r][1] += w * h1;
                }
            }
        } else {
            // phase A: register f32 weights, cols [0,512)
#pragma unroll
            for (int j = 0; j < 16; j++) {
                int k = lane + 32 * j;
                float h0 = sh_h[k], h1 = sh_h[EMB + k];
#pragma unroll
                for (int r = 0; r < RPW; r++) {
                    float w = wreg[r][j];
                    acc[r][0] += w * h0; acc[r][1] += w * h1;
                }
            }
            // phase B: smem fp16 weights, cols [512,2048) as pairs
#pragma unroll 4
            for (int jp = 0; jp < 24; jp++) {
                int p = lane + 32 * jp;          // pair index in [0,768)
                int c = 512 + 2 * p;
                float2 hA = *(const float2*)&sh_h[c];
                float2 hB = *(const float2*)&sh_h[EMB + c];
#pragma unroll
                for (int r = 0; r < RPW; r++) {
                    unsigned wv = sh_w[rl[r] * 768 + p];
                    float2 wf = __half22float2(*(__half2*)&wv);
                    acc[r][0] += wf.x * hA.x; acc[r][0] += wf.y * hA.y;
                    acc[r][1] += wf.x * hB.x; acc[r][1] += wf.y * hB.y;
                }
            }
        }

        // warp reduce + write gate values
#pragma unroll
        for (int r = 0; r < RPW; r++)
#pragma unroll
            for (int b = 0; b < 2; b++) {
                float v = acc[r][b];
                v += __shfl_xor_sync(0xffffffffu, v, 16);
                v += __shfl_xor_sync(0xffffffffu, v, 8);
                v += __shfl_xor_sync(0xffffffffu, v, 4);
                v += __shfl_xor_sync(0xffffffffu, v, 2);
                v += __shfl_xor_sync(0xffffffffu, v, 1);
                if (lane == 0) sh_g[rl[r] * 2 + b] = v + bias[r];
            }
        __syncthreads();

        // owners: activation + state update + publish h
        if (tid < 32) {
            float gi = sh_g[(0  + my_el) * 2 + my_b];
            float gf = sh_g[(16 + my_el) * 2 + my_b];
            float gg = sh_g[(32 + my_el) * 2 + my_b];
            float go = sh_g[(48 + my_el) * 2 + my_b];
            float cn = sigmoidf_(gf) * c_reg + sigmoidf_(gi) * tanhf(gg);
            c_reg = cn;
            float h = sigmoidf_(go) * tanhf(cn);
            g_hseq[((size_t)t * NB + my_b) * EMB + e0 + my_el] = h;
        }
        __threadfence();
        __syncthreads();

        // grid barrier (R1-proven): single counter
        if (tid == 0) {
            atomicAdd(&g_bar, 1u);
            unsigned target = (unsigned)(t + 1) * gridDim.x;
            while (*((volatile unsigned*)&g_bar) < target) { }
            __threadfence();
        }
        __syncthreads();
    }
}

// ---------------------------------------------------------------------------
// output projection: out[b][t][n] = hseq[t][b][:] . W_out[n][:] + b_out[n]
// M = 4096 (m = t*2+b), N = 2048, K = 2048 (scalar FFMA, R1-proven)
// ---------------------------------------------------------------------------
#define GBM 64
#define GBN 64
#define GBK 16
#define GPAD 4

__global__ void __launch_bounds__(256)
out_gemm_kernel(const float* __restrict__ Wout, const float* __restrict__ bout,
                float* __restrict__ out) {
    __shared__ float As[GBK][GBM + GPAD];
    __shared__ float Bs[GBK][GBN + GPAD];

    const int tid = threadIdx.x;
    const int tx = tid & 15;
    const int ty = tid >> 4;
    const int m0 = blockIdx.y * GBM;
    const int n0 = blockIdx.x * GBN;

    float acc[4][4];
#pragma unroll
    for (int i = 0; i < 4; i++)
#pragma unroll
        for (int j = 0; j < 4; j++) acc[i][j] = 0.0f;

    const int lm = tid >> 2;
    const int lk = (tid & 3) * 4;

    for (int k0 = 0; k0 < EMB; k0 += GBK) {
        float4 va = *(const float4*)&g_hseq[(size_t)(m0 + lm) * EMB + k0 + lk];
        float4 vb = *(const float4*)&Wout[(size_t)(n0 + lm) * EMB + k0 + lk];
        As[lk + 0][lm] = va.x; As[lk + 1][lm] = va.y;
        As[lk + 2][lm] = va.z; As[lk + 3][lm] = va.w;
        Bs[lk + 0][lm] = vb.x; Bs[lk + 1][lm] = vb.y;
        Bs[lk + 2][lm] = vb.z; Bs[lk + 3][lm] = vb.w;
        __syncthreads();

#pragma unroll
        for (int k = 0; k < GBK; k++) {
            float a0 = As[k][ty * 4 + 0];
            float a1 = As[k][ty * 4 + 1];
            float a2 = As[k][ty * 4 + 2];
            float a3 = As[k][ty * 4 + 3];
            float4 b4 = *(const float4*)&Bs[k][tx * 4];
            acc[0][0] += a0 * b4.x; acc[0][1] += a0 * b4.y; acc[0][2] += a0 * b4.z; acc[0][3] += a0 * b4.w;
            acc[1][0] += a1 * b4.x; acc[1][1] += a1 * b4.y; acc[1][2] += a1 * b4.z; acc[1][3] += a1 * b4.w;
            acc[2][0] += a2 * b4.x; acc[2][1] += a2 * b4.y; acc[2][2] += a2 * b4.z; acc[2][3] += a2 * b4.w;
            acc[3][0] += a3 * b4.x; acc[3][1] += a3 * b4.y; acc[3][2] += a3 * b4.z; acc[3][3] += a3 * b4.w;
        }
        __syncthreads();
    }

#pragma unroll
    for (int i = 0; i < 4; i++) {
        int m = m0 + ty * 4 + i;
        int tt = m >> 1, bb = m & 1;
#pragma unroll
        for (int j = 0; j < 4; j++) {
            int n = n0 + tx * 4 + j;
            out[((size_t)bb * NSTEP + tt) * EMB + n] = acc[i][j] + bout[n];
        }
    }
}

// ---------------------------------------------------------------------------
extern "C" void kernel_launch(void* const* d_in, const int* in_sizes, int n_in,
                              void* d_out, int out_size) {
    const float* x    = (const float*)d_in[0];
    const float* Wih  = (const float*)d_in[1];
    const float* Whh  = (const float*)d_in[2];
    const float* bih  = (const float*)d_in[3];
    const float* bhh  = (const float*)d_in[4];
    const float* Wout = (const float*)d_in[5];
    const float* bout = (const float*)d_in[6];
    float* out = (float*)d_out;

    cudaFuncSetAttribute(lstm_kernel, cudaFuncAttributeMaxDynamicSharedMemorySize, SMEM_BYTES);

    prep_kernel<<<4096, 256>>>(Wih, Whh, bih, bhh);
    lstm_kernel<<<CTAS, NTHR, SMEM_BYTES>>>(x, Wih);
    dim3 ggrid(EMB / GBN, (NSTEP * NB) / GBM);
    out_gemm_kernel<<<ggrid, 256>>>(Wout, bout, out);
}

// round 7
// speedup vs baseline: 2.4483x; 1.0149x over previous
#include <cuda_runtime.h>
#include <cuda_fp16.h>

#define EMB   2048
#define NSTEP 2048
#define NB    2
#define G4    (4*EMB)

#define CTAS  128
#define EPC   16          // e-values per CTA
#define NROWS 64          // 4 gates * EPC
#define NTHR  512         // 16 warps
#define RPW   4           // rows per warp, each warp covers full K

// K partition per row (2048 cols):
//   cols [0,512)     f32 in registers  (pair q = lane + 32*j, j in [0,8), col=2q)
//   cols [512,2048)  fp16 in smem      (uint2 pp = lane + 32*m, m in [0,12), col=512+4pp)

#define SH_W_U (NROWS*768)          // 49152 uints (fp16x2) = 192KB
#define SH_H_F (NB*EMB)             // 4096 floats = 16KB
#define SH_G_F (NROWS*2)
#define SMEM_BYTES (SH_W_U*4 + SH_H_F*4 + SH_G_F*4)

__device__ float  g_Wcomb[(size_t)G4*EMB];      // f32 Wih+Whh
__device__ __half g_Whalf[(size_t)G4*EMB];      // fp16 copy
__device__ float  g_bcomb[G4];
__device__ float  g_hseq[(size_t)NSTEP*NB*EMB]; // [t][b][e]
__device__ unsigned g_bar;

__device__ __forceinline__ float sigmoidf_(float v) {
    return 1.0f / (1.0f + expf(-v));
}

// ---------------------------------------------------------------------------
__global__ void prep_kernel(const float* __restrict__ Wih, const float* __restrict__ Whh,
                            const float* __restrict__ bih, const float* __restrict__ bhh) {
    size_t n = (size_t)G4 * EMB;
    size_t stride = (size_t)gridDim.x * blockDim.x;
    for (size_t i = (size_t)blockIdx.x * blockDim.x + threadIdx.x; i < n; i += stride) {
        float v = Wih[i] + Whh[i];
        g_Wcomb[i] = v;
        g_Whalf[i] = __float2half(v);
    }
    int i = blockIdx.x * blockDim.x + threadIdx.x;
    if (i < G4) g_bcomb[i] = bih[i] + bhh[i];
    if (i == 0) g_bar = 0u;
}

// ---------------------------------------------------------------------------
// persistent LSTM: 128 CTAs x 512 threads (16 warps, 4/SMSP), occupancy 1.
// Warp w owns rows w*4..w*4+3 over the FULL K. No steady-state global weight
// reads: cols [0,512) in registers (f32), cols [512,2048) in smem (fp16).
// ---------------------------------------------------------------------------
__global__ void __launch_bounds__(NTHR, 1)
lstm_kernel(const float* __restrict__ x, const float* __restrict__ Wih) {
    extern __shared__ float sh[];
    unsigned* sh_w = (unsigned*)sh;          // [64][768] fp16x2, cols [512,2048)
    float* sh_h = sh + SH_W_U;               // [2][2048]
    float* sh_g = sh_h + SH_H_F;             // [64][2]

    const int tid  = threadIdx.x;
    const int lane = tid & 31;
    const int wid  = tid >> 5;
    const int e0   = blockIdx.x * EPC;

    int rl[RPW], Rg[RPW];
    float bias[RPW];
#pragma unroll
    for (int r = 0; r < RPW; r++) {
        rl[r] = wid * RPW + r;
        int gate = rl[r] >> 4, e_l = rl[r] & 15;
        Rg[r] = gate * EMB + e0 + e_l;
        bias[r] = g_bcomb[Rg[r]];
    }

    // fill smem fp16 weights: cols [512,2048) for the CTA's 64 rows
    {
        const int n4 = NROWS * 192;          // uint4 count (8 halves each)
        for (int i = tid; i < n4; i += NTHR) {
            int rr = i / 192, q4 = i % 192;
            int grow = (rr >> 4) * EMB + e0 + (rr & 15);
            uint4 v = *(const uint4*)&g_Whalf[(size_t)grow * EMB + 512 + q4 * 8];
            ((uint4*)sh_w)[rr * 192 + q4] = v;
        }
    }

    // register-resident f32 weight pairs: col = 2*(lane + 32*j), j in [0,8)
    float2 wreg[RPW][8];
#pragma unroll
    for (int r = 0; r < RPW; r++)
#pragma unroll
        for (int j = 0; j < 8; j++)
            wreg[r][j] = *(const float2*)&g_Wcomb[(size_t)Rg[r] * EMB + 2 * (lane + 32 * j)];

    float c_reg = 0.0f;
    const int my_el = tid >> 1, my_b = tid & 1;

    for (int t = 0; t < NSTEP; t++) {
        // stage h_{t-1} (or x) into smem
        const float* src = (t == 0) ? x : &g_hseq[(size_t)(t - 1) * NB * EMB];
        {
            const float4* s4 = (const float4*)src;
            float4* d4 = (float4*)sh_h;
            d4[tid]        = __ldcg(s4 + tid);
            d4[tid + NTHR] = __ldcg(s4 + tid + NTHR);
        }
        __syncthreads();

        float acc[RPW][2];
#pragma unroll
        for (int r = 0; r < RPW; r++) { acc[r][0] = 0.0f; acc[r][1] = 0.0f; }

        if (t == 0) {
            // gates0 = x @ W_ih^T (h0 = 0): stream W_ih f32 once
#pragma unroll 4
            for (int j = 0; j < 64; j++) {
                int k = lane + 32 * j;
                float h0 = sh_h[k], h1 = sh_h[EMB + k];
#pragma unroll
                for (int r = 0; r < RPW; r++) {
                    float w = __ldg(&Wih[(size_t)Rg[r] * EMB + k]);
                    acc[r][0] += w * h0; acc[r][1] += w * h1;
                }
            }
        } else {
            // phase A: register f32 weight pairs, cols [0,512)
#pragma unroll
            for (int j = 0; j < 8; j++) {
                int c = 2 * (lane + 32 * j);
                float2 hA = *(const float2*)&sh_h[c];
                float2 hB = *(const float2*)&sh_h[EMB + c];
#pragma unroll
                for (int r = 0; r < RPW; r++) {
                    float2 w = wreg[r][j];
                    acc[r][0] += w.x * hA.x; acc[r][0] += w.y * hA.y;
                    acc[r][1] += w.x * hB.x; acc[r][1] += w.y * hB.y;
                }
            }
            // phase B: smem fp16 weights, cols [512,2048), 4 cols/iter
            const uint2* sw2 = (const uint2*)sh_w;
#pragma unroll 4
            for (int m = 0; m < 12; m++) {
                int pp = lane + 32 * m;          // uint2 index in [0,384)
                int c = 512 + 4 * pp;
                float4 hA = *(const float4*)&sh_h[c];
                float4 hB = *(const float4*)&sh_h[EMB + c];
#pragma unroll
                for (int r = 0; r < RPW; r++) {
                    uint2 wv = sw2[rl[r] * 384 + pp];
                    float2 w0 = __half22float2(*(__half2*)&wv.x);
                    float2 w1 = __half22float2(*(__half2*)&wv.y);
                    acc[r][0] += w0.x * hA.x; acc[r][0] += w0.y * hA.y;
                    acc[r][0] += w1.x * hA.z; acc[r][0] += w1.y * hA.w;
                    acc[r][1] += w0.x * hB.x; acc[r][1] += w0.y * hB.y;
                    acc[r][1] += w1.x * hB.z; acc[r][1] += w1.y * hB.w;
                }
            }
        }

        // warp reduce + write gate pre-activations (bias included)
#pragma unroll
        for (int r = 0; r < RPW; r++)
#pragma unroll
            for (int b = 0; b < 2; b++) {
                float v = acc[r][b];
                v += __shfl_xor_sync(0xffffffffu, v, 16);
                v += __shfl_xor_sync(0xffffffffu, v, 8);
                v += __shfl_xor_sync(0xffffffffu, v, 4);
                v += __shfl_xor_sync(0xffffffffu, v, 2);
                v += __shfl_xor_sync(0xffffffffu, v, 1);
                if (lane == 0) sh_g[rl[r] * 2 + b] = v + bias[r];
            }
        __syncthreads();

        // 128 threads apply the gate nonlinearities in parallel
        if (tid < 128) {
            int gate = tid >> 5, idx = tid & 31;
            int el = idx >> 1, b = idx & 1;
            float v = sh_g[(gate * 16 + el) * 2 + b];
            sh_g[(gate * 16 + el) * 2 + b] = (gate == 2) ? tanhf(v) : sigmoidf_(v);
        }
        __syncthreads();

        // owners: combine + publish h
        if (tid < 32) {
            float ai = sh_g[(0  + my_el) * 2 + my_b];
            float af = sh_g[(16 + my_el) * 2 + my_b];
            float ag = sh_g[(32 + my_el) * 2 + my_b];
            float ao = sh_g[(48 + my_el) * 2 + my_b];
            float cn = af * c_reg + ai * ag;
            c_reg = cn;
            float h = ao * tanhf(cn);
            g_hseq[((size_t)t * NB + my_b) * EMB + e0 + my_el] = h;
        }
        __threadfence();
        __syncthreads();

        // grid barrier: single counter
        if (tid == 0) {
            atomicAdd(&g_bar, 1u);
            unsigned target = (unsigned)(t + 1) * gridDim.x;
            while (*((volatile unsigned*)&g_bar) < target) { }
            __threadfence();
        }
        __syncthreads();
    }
}

// ---------------------------------------------------------------------------
// output projection: out[b][t][n] = hseq[t][b][:] . W_out[n][:] + b_out[n]
// M = 4096 (m = t*2+b), N = 2048, K = 2048. 128x128x16 tile, 8x8/thread.
// ---------------------------------------------------------------------------
#define TBM 128
#define TBN 128
#define TBK 16
#define TPAD 4

__global__ void __launch_bounds__(256, 2)
out_gemm_kernel(const float* __restrict__ Wout, const float* __restrict__ bout,
                float* __restrict__ out) {
    __shared__ float As[TBK][TBM + TPAD];
    __shared__ float Bs[TBK][TBN + TPAD];

    const int tid = threadIdx.x;
    const int tx = tid & 15;     // n dir (8 cols each)
    const int ty = tid >> 4;     // m dir (8 rows each)
    const int m0 = blockIdx.y * TBM;
    const int n0 = blockIdx.x * TBN;

    float acc[8][8];
#pragma unroll
    for (int i = 0; i < 8; i++)
#pragma unroll
        for (int j = 0; j < 8; j++) acc[i][j] = 0.0f;

    for (int k0 = 0; k0 < EMB; k0 += TBK) {
        // load 128x16 A and B tiles: 512 float4 each, 2 per thread
#pragma unroll
        for (int u = 0; u < 2; u++) {
            int fi = tid * 2 + u;           // float4 index in [0,512)
            int row = fi >> 2;              // tile row
            int kc = (fi & 3) * 4;          // k within tile
            float4 va = *(const float4*)&g_hseq[(size_t)(m0 + row) * EMB + k0 + kc];
            As[kc + 0][row] = va.x; As[kc + 1][row] = va.y;
            As[kc + 2][row] = va.z; As[kc + 3][row] = va.w;
            float4 vb = *(const float4*)&Wout[(size_t)(n0 + row) * EMB + k0 + kc];
            Bs[kc + 0][row] = vb.x; Bs[kc + 1][row] = vb.y;
            Bs[kc + 2][row] = vb.z; Bs[kc + 3][row] = vb.w;
        }
        __syncthreads();

#pragma unroll
        for (int k = 0; k < TBK; k++) {
            float a[8], b[8];
            *(float4*)&a[0] = *(const float4*)&As[k][ty * 8];
            *(float4*)&a[4] = *(const float4*)&As[k][ty * 8 + 4];
            *(float4*)&b[0] = *(const float4*)&Bs[k][tx * 8];
            *(float4*)&b[4] = *(const float4*)&Bs[k][tx * 8 + 4];
#pragma unroll
            for (int i = 0; i < 8; i++)
#pragma unroll
                for (int j = 0; j < 8; j++)
                    acc[i][j] += a[i] * b[j];
        }
        __syncthreads();
    }

    float bo[8];
#pragma unroll
    for (int j = 0; j < 8; j++) bo[j] = bout[n0 + tx * 8 + j];

#pragma unroll
    for (int i = 0; i < 8; i++) {
        int m = m0 + ty * 8 + i;
        int tt = m >> 1, bb = m & 1;
        float* o = &out[((size_t)bb * NSTEP + tt) * EMB + n0 + tx * 8];
#pragma unroll
        for (int j = 0; j < 8; j += 4) {
            float4 v;
            v.x = acc[i][j + 0] + bo[j + 0];
            v.y = acc[i][j + 1] + bo[j + 1];
            v.z = acc[i][j + 2] + bo[j + 2];
            v.w = acc[i][j + 3] + bo[j + 3];
            *(float4*)&o[j] = v;
        }
    }
}

// ---------------------------------------------------------------------------
extern "C" void kernel_launch(void* const* d_in, const int* in_sizes, int n_in,
                              void* d_out, int out_size) {
    const float* x    = (const float*)d_in[0];
    const float* Wih  = (const float*)d_in[1];
    const float* Whh  = (const float*)d_in[2];
    const float* bih  = (const float*)d_in[3];
    const float* bhh  = (const float*)d_in[4];
    const float* Wout = (const float*)d_in[5];
    const float* bout = (const float*)d_in[6];
    float* out = (float*)d_out;

    cudaFuncSetAttribute(lstm_kernel, cudaFuncAttributeMaxDynamicSharedMemorySize, SMEM_BYTES);

    prep_kernel<<<4096, 256>>>(Wih, Whh, bih, bhh);
    lstm_kernel<<<CTAS, NTHR, SMEM_BYTES>>>(x, Wih);
    dim3 ggrid(EMB / TBN, (NSTEP * NB) / TBM);
    out_gemm_kernel<<<ggrid, 256>>>(Wout, bout, out);
}